// round 7
// baseline (speedup 1.0000x reference)
#include <cuda_runtime.h>
#include <cuda_bf16.h>
#include <cstdint>
#include <cstddef>

#define BB 2
#define NN 256
#define DD 256

// ---------------------------------------------------------------------------
// PTX helpers (sm_80+ paths; compile clean for plain sm_100)
// ---------------------------------------------------------------------------
__device__ __forceinline__ uint32_t smem_u32(const void* p) {
    uint32_t a;
    asm("{ .reg .u64 t; cvta.to.shared.u64 t, %1; cvt.u32.u64 %0, t; }" : "=r"(a) : "l"(p));
    return a;
}
__device__ __forceinline__ void ldsm_x4(uint32_t* r, uint32_t addr) {
    asm volatile("ldmatrix.sync.aligned.m8n8.x4.shared.b16 {%0,%1,%2,%3}, [%4];"
                 : "=r"(r[0]), "=r"(r[1]), "=r"(r[2]), "=r"(r[3]) : "r"(addr));
}
__device__ __forceinline__ void mma_bf16(float* c, const uint32_t* a, const uint32_t* b) {
    asm volatile(
        "mma.sync.aligned.m16n8k16.row.col.f32.bf16.bf16.f32 "
        "{%0,%1,%2,%3}, {%4,%5,%6,%7}, {%8,%9}, {%0,%1,%2,%3};"
        : "+f"(c[0]), "+f"(c[1]), "+f"(c[2]), "+f"(c[3])
        : "r"(a[0]), "r"(a[1]), "r"(a[2]), "r"(a[3]), "r"(b[0]), "r"(b[1]));
}
__device__ __forceinline__ void cp16(uint32_t saddr, const void* gptr) {
    asm volatile("cp.async.cg.shared.global [%0], [%1], 16;" :: "r"(saddr), "l"(gptr));
}
__device__ __forceinline__ void cp_commit() { asm volatile("cp.async.commit_group;"); }
__device__ __forceinline__ void cp_wait_all() { asm volatile("cp.async.wait_group 0;"); }

// ---------------------------------------------------------------------------
// Device scratch
// ---------------------------------------------------------------------------
__device__ float g_xi[BB * NN * DD];
__device__ float g_xj[BB * NN * DD];
__device__ float g_wviT[DD * DD];           // w_vi transposed [k][d]
__device__ float g_wvjT[DD * DD];           // w_vj transposed [k][d]
__device__ float g_part[2 * 8 * BB * NN * DD / 4];  // split-k partials [mat][ks][row][k]... sized below
// NOTE: need [2][8][512][256] floats = 2097152 floats
__device__ float g_partials[2 * 8 * 512 * 256];
// w_alpha split bf16 hi/lo, kstep-chunked: [ks][n] -> 64B = [16 hi][16 lo]
__device__ uint4 g_wB[16 * 256 * 4];        // 262144 bytes

// ---------------------------------------------------------------------------
// SMEM layout (bytes), main kernel. 1 CTA/SM (174080 B).
//   sA: 2 buffers x (64 rows x 512B swizzled; hi at +0, lo at +32768)
//   sB: 2 bufs x (256 n x 80B rows: [32B hi][32B lo][16B pad])
//   red (2KB) aliases sB buf0 (only used after all MMA done)
// ---------------------------------------------------------------------------
#define SM_ABUF  65536
#define SM_ALO   32768
#define SM_B     131072
#define SB_BUF   20480
#define SM_XI    172032
#define SM_ADJ   173056
#define SM_RED   SM_B
#define SMEM_BYTES 174080

// ---------------------------------------------------------------------------
// P1: wconv (blocks 0..255) + transpose w_vi/w_vj (blocks 256..383)
// ---------------------------------------------------------------------------
__global__ void __launch_bounds__(256) prep1_kernel(const float* __restrict__ w_alpha,
                                                    const float* __restrict__ w_vi,
                                                    const float* __restrict__ w_vj)
{
    const int bid = blockIdx.x;
    const int tid = threadIdx.x;
    if (bid < 256) {
        // split w_alpha into bf16 hi/lo, kstep-chunked layout
        const int idx = bid * 256 + tid;      // d*256 + n
        const int d = idx >> 8;
        const int n = idx & 255;
        const float v = w_alpha[idx];
        const __nv_bfloat16 hi = __float2bfloat16(v);
        const __nv_bfloat16 lo = __float2bfloat16(v - __bfloat162float(hi));
        __nv_bfloat16* wb = (__nv_bfloat16*)g_wB;
        const int base = (d >> 4) * 8192 + n * 32 + (d & 15);
        wb[base]      = hi;
        wb[base + 16] = lo;
    } else {
        // transpose 32x32 tile of w_vi or w_vj
        const int m = bid - 256;              // 0..127
        const float* src = (m < 64) ? w_vi : w_vj;
        float* dst = (m < 64) ? g_wviT : g_wvjT;
        const int t2 = m & 63;
        const int r0 = (t2 >> 3) * 32;
        const int c0 = (t2 & 7) * 32;
        __shared__ float tile[32][33];
        const int tx = tid & 31, ty = tid >> 5;  // ty 0..7
#pragma unroll
        for (int i = 0; i < 4; i++)
            tile[ty + i * 8][tx] = src[(r0 + ty + i * 8) * DD + c0 + tx];
        __syncthreads();
#pragma unroll
        for (int i = 0; i < 4; i++)
            dst[(c0 + ty + i * 8) * DD + r0 + tx] = tile[tx][ty + i * 8];
    }
}

// ---------------------------------------------------------------------------
// P2: split-k projection partials. grid 256: rb = bid>>3 (16-row block),
// ksb = bid&7 (32-d slice). Thread = output column k.
// ---------------------------------------------------------------------------
__global__ void __launch_bounds__(256) prep2_kernel(const float* __restrict__ x)
{
    __shared__ float sX[16][32];
    const int bid = blockIdx.x;
    const int tid = threadIdx.x;
    const int r0 = (bid >> 3) * 16;
    const int d0 = (bid & 7) * 32;
    {
        int idx = tid;
#pragma unroll
        for (int p = 0; p < 2; p++) {
            const int r = idx >> 5, d = idx & 31;
            sX[r][d] = x[(r0 + r) * DD + d0 + d];
            idx += 256;
        }
    }
    __syncthreads();

    const int k = tid;
    float ai[16], aj[16];
#pragma unroll
    for (int r = 0; r < 16; r++) { ai[r] = 0.f; aj[r] = 0.f; }

    const float4* wv = (const float4*)(g_wviT + k * DD + d0);
    const float4* wj = (const float4*)(g_wvjT + k * DD + d0);
#pragma unroll
    for (int q = 0; q < 8; q++) {
        const float4 v = wv[q];
        const float4 w = wj[q];
#pragma unroll
        for (int r = 0; r < 16; r++) {
            const float4 xr = *(const float4*)(&sX[r][q * 4]);
            ai[r] = fmaf(xr.x, v.x, ai[r]);
            ai[r] = fmaf(xr.y, v.y, ai[r]);
            ai[r] = fmaf(xr.z, v.z, ai[r]);
            ai[r] = fmaf(xr.w, v.w, ai[r]);
            aj[r] = fmaf(xr.x, w.x, aj[r]);
            aj[r] = fmaf(xr.y, w.y, aj[r]);
            aj[r] = fmaf(xr.z, w.z, aj[r]);
            aj[r] = fmaf(xr.w, w.w, aj[r]);
        }
    }
    const int ksb = bid & 7;
#pragma unroll
    for (int r = 0; r < 16; r++) {
        g_partials[((0 * 8 + ksb) * 512 + r0 + r) * 256 + k] = ai[r];
        g_partials[((1 * 8 + ksb) * 512 + r0 + r) * 256 + k] = aj[r];
    }
}

// ---------------------------------------------------------------------------
// P3: reduce split-k partials -> g_xi, g_xj. grid 512 (row), 256 thr (k).
// ---------------------------------------------------------------------------
__global__ void __launch_bounds__(256) prep3_kernel()
{
    const int row = blockIdx.x;
    const int k = threadIdx.x;
    float xi = 0.f, xj = 0.f;
#pragma unroll
    for (int ks = 0; ks < 8; ks++) {
        xi += g_partials[((0 * 8 + ks) * 512 + row) * 256 + k];
        xj += g_partials[((1 * 8 + ks) * 512 + row) * 256 + k];
    }
    g_xi[row * DD + k] = xi;
    g_xj[row * DD + k] = xj;
}

// ---------------------------------------------------------------------------
// Main kernel pieces
// ---------------------------------------------------------------------------
struct BP { float2 a0, x0, b0, a1, x1, b1; };

__device__ __forceinline__ void build_prefetch(BP& p,
                                               const float* __restrict__ alpha_base,
                                               const float* __restrict__ xjB,
                                               const float* __restrict__ biasB,
                                               int j0, int r0, int tid)
{
    const int d0  = (tid & 127) * 2;
    const int par = tid >> 7;
    const size_t off0 = (size_t)(j0 + r0 + par) * DD + d0;
    const size_t off1 = (size_t)(j0 + r0 + 2 + par) * DD + d0;
    p.a0 = *(const float2*)(alpha_base + off0);
    p.x0 = *(const float2*)(xjB + off0);
    p.b0 = *(const float2*)(biasB + off0);
    p.a1 = *(const float2*)(alpha_base + off1);
    p.x1 = *(const float2*)(xjB + off1);
    p.b1 = *(const float2*)(biasB + off1);
}

__device__ __forceinline__ void build_finalize(char* smem, int abuf, const BP& p,
                                               int j0, int r0, int tid,
                                               float& ah0, float& ah1)
{
    const float* sXi  = (const float*)(smem + SM_XI);
    const float* sAdj = (const float*)(smem + SM_ADJ);
    const int d0  = (tid & 127) * 2;
    const int par = tid >> 7;
    const float xi0 = sXi[d0], xi1 = sXi[d0 + 1];
    const uint32_t u   = (uint32_t)(tid & 127) >> 2;
    const uint32_t inB = (uint32_t)((tid & 127) & 3) * 4;
    char* base = smem + abuf * SM_ABUF;
#pragma unroll
    for (int it = 0; it < 2; it++) {
        const int jj = r0 + it * 2 + par;       // tile-local row
        const float2 av = it ? p.a1 : p.a0;
        const float2 xv = it ? p.x1 : p.x0;
        const float2 bv = it ? p.b1 : p.b0;
        const float h0 = fmaxf(av.x + xv.x + bv.x + xi0, 0.f);
        const float h1 = fmaxf(av.y + xv.y + bv.y + xi1, 0.f);
        const float aw = sAdj[j0 + jj];
        ah0 = fmaf(aw, h0, ah0);
        ah1 = fmaf(aw, h1, ah1);
        const __nv_bfloat16 hh0 = __float2bfloat16(h0);
        const __nv_bfloat16 hh1 = __float2bfloat16(h1);
        const __nv_bfloat16 hl0 = __float2bfloat16(h0 - __bfloat162float(hh0));
        const __nv_bfloat16 hl1 = __float2bfloat16(h1 - __bfloat162float(hh1));
        const uint32_t hp = ((uint32_t)__bfloat16_as_ushort(hh1) << 16) | __bfloat16_as_ushort(hh0);
        const uint32_t lp = ((uint32_t)__bfloat16_as_ushort(hl1) << 16) | __bfloat16_as_ushort(hl0);
        const uint32_t addr = (uint32_t)jj * 512u + ((u ^ (uint32_t)(jj & 7)) << 4) + inB;
        *(uint32_t*)(base + addr) = hp;
        *(uint32_t*)(base + SM_ALO + addr) = lp;
    }
}

__device__ __forceinline__ void stage_B_async(uint32_t sb, int ks, int buf, int tid)
{
    const char* g = (const char*)g_wB + (size_t)ks * 16384 + (size_t)tid * 64;
    const uint32_t s = sb + SM_B + (uint32_t)buf * SB_BUF + (uint32_t)tid * 80;
    cp16(s,      g);
    cp16(s + 16, g + 16);
    cp16(s + 32, g + 32);
    cp16(s + 48, g + 48);
    cp_commit();
}

__global__ void __launch_bounds__(256) main_kernel(
    const float* __restrict__ alpha,
    const float* __restrict__ adj,
    const float* __restrict__ bias_h,
    const float* __restrict__ w_node,
    float* __restrict__ out_x,
    float* __restrict__ out_alpha)
{
    extern __shared__ char smem[];
    const uint32_t sb = smem_u32(smem);
    const int tid  = threadIdx.x;
    const int wid  = tid >> 5;
    const int lane = tid & 31;
    const int rg = wid & 1;         // 32-row group
    const int cg = wid >> 1;        // 64-col group
    const size_t bi = blockIdx.x;
    const int b = (int)(bi >> 8);

    ((float*)(smem + SM_XI))[tid]  = g_xi[bi * DD + tid];
    ((float*)(smem + SM_ADJ))[tid] = adj[bi * NN + tid];
    __syncthreads();

    const float* alpha_base = alpha + bi * (size_t)NN * DD;
    const float* xjB = g_xj + (size_t)b * NN * DD;

    // A ldsm addressing
    const int rowA = rg * 32 + (lane & 15);
    const uint32_t r7 = (uint32_t)(rowA & 7);
    const uint32_t hilo = (uint32_t)(lane >> 4);
    // B ldsm addressing (x4 covers nb pair)
    const uint32_t nrow = (uint32_t)(cg * 64 + (lane & 7) + ((lane & 16) >> 1));
    const uint32_t bBase = sb + SM_B + nrow * 80u + (uint32_t)((lane >> 3) & 1) * 16u;

    float ah0 = 0.f, ah1 = 0.f;
    float acc[2][8][4];

    // ---- prologue: stage B ks0, build full tile 0 into A buf 0 ----
    stage_B_async(sb, 0, 0, tid);
#pragma unroll 1
    for (int r0 = 0; r0 < 64; r0 += 4) {
        BP p;
        build_prefetch(p, alpha_base, xjB, bias_h, 0, r0, tid);
        build_finalize(smem, 0, p, 0, r0, tid, ah0, ah1);
    }
    cp_wait_all();
    __syncthreads();

#pragma unroll 1
    for (int t = 0; t < 4; t++) {
        const int abuf = t & 1;
        const uint32_t aBase = sb + (uint32_t)abuf * SM_ABUF + (uint32_t)rowA * 512u;
#pragma unroll
        for (int mb = 0; mb < 2; mb++)
#pragma unroll
            for (int nb = 0; nb < 8; nb++)
#pragma unroll
                for (int q = 0; q < 4; q++) acc[mb][nb][q] = 0.f;

        const bool doBuild = (t < 3);
        const int j0n = (t + 1) * 64;

#pragma unroll 1
        for (int ks = 0; ks < 16; ks++) {
            const int buf = ks & 1;
            stage_B_async(sb, (ks + 1) & 15, buf ^ 1, tid);

            BP p;
            if (doBuild) build_prefetch(p, alpha_base, xjB, bias_h, j0n, ks * 4, tid);

            const uint32_t aOff = (((uint32_t)(ks * 2) + hilo) ^ r7) << 4;
            uint32_t Ah0[4], Ah1[4], Al0[4], Al1[4];
            ldsm_x4(Ah0, aBase + aOff);
            ldsm_x4(Ah1, aBase + 16 * 512 + aOff);
            ldsm_x4(Al0, aBase + SM_ALO + aOff);
            ldsm_x4(Al1, aBase + SM_ALO + 16 * 512 + aOff);

            const uint32_t bBuf = bBase + (uint32_t)buf * SB_BUF;
#pragma unroll
            for (int nbp = 0; nbp < 4; nbp++) {
                uint32_t Bh[4], Bl[4];
                ldsm_x4(Bh, bBuf + (uint32_t)nbp * 1280u);
                ldsm_x4(Bl, bBuf + (uint32_t)nbp * 1280u + 32u);
                const int nb = nbp * 2;
                mma_bf16(acc[0][nb],     Ah0, Bh);
                mma_bf16(acc[0][nb],     Al0, Bh);
                mma_bf16(acc[0][nb],     Ah0, Bl);
                mma_bf16(acc[1][nb],     Ah1, Bh);
                mma_bf16(acc[1][nb],     Al1, Bh);
                mma_bf16(acc[1][nb],     Ah1, Bl);
                mma_bf16(acc[0][nb + 1], Ah0, Bh + 2);
                mma_bf16(acc[0][nb + 1], Al0, Bh + 2);
                mma_bf16(acc[0][nb + 1], Ah0, Bl + 2);
                mma_bf16(acc[1][nb + 1], Ah1, Bh + 2);
                mma_bf16(acc[1][nb + 1], Al1, Bh + 2);
                mma_bf16(acc[1][nb + 1], Ah1, Bl + 2);
            }

            if (doBuild) build_finalize(smem, abuf ^ 1, p, j0n, ks * 4, tid, ah0, ah1);

            cp_wait_all();
            __syncthreads();
        }

        // epilogue tile t (register-only source)
        {
            const int j0 = t * 64;
            const int r0 = rg * 32 + (lane >> 2);
            const int c0 = cg * 64 + (lane & 3) * 2;
#pragma unroll
            for (int mb = 0; mb < 2; mb++) {
#pragma unroll
                for (int nb = 0; nb < 8; nb++) {
                    float* base = out_alpha + ((size_t)bi * NN + j0 + r0 + mb * 16) * DD + c0 + nb * 8;
                    float2 v0, v1;
                    v0.x = fmaxf(acc[mb][nb][0], 0.f);
                    v0.y = fmaxf(acc[mb][nb][1], 0.f);
                    v1.x = fmaxf(acc[mb][nb][2], 0.f);
                    v1.y = fmaxf(acc[mb][nb][3], 0.f);
                    *(float2*)base = v0;
                    *(float2*)(base + 8 * DD) = v1;
                }
            }
        }
    }

    // ---- AH reduce + new_x (red aliases sB buf0; safe after final sync) ----
    __syncthreads();
    {
        float* red = (float*)(smem + SM_RED);
        const int d0  = (tid & 127) * 2;
        const int par = tid >> 7;
        red[par * 256 + d0]     = ah0;
        red[par * 256 + d0 + 1] = ah1;
    }
    __syncthreads();
    {
        const float* red = (const float*)(smem + SM_RED);
        float acc2 = 0.f;
#pragma unroll 8
        for (int d = 0; d < DD; d++)
            acc2 = fmaf(red[d] + red[256 + d], w_node[d * DD + tid], acc2);
        out_x[bi * DD + tid] = fmaxf(acc2, 0.f);
    }
}

// ---------------------------------------------------------------------------
// Launch. Inputs: x, alpha, adj, w_alpha, w_vi, w_vj, bias_h, w_node
// Output: new_x (131072 f32) then new_alpha (33554432 f32)
// ---------------------------------------------------------------------------
extern "C" void kernel_launch(void* const* d_in, const int* in_sizes, int n_in,
                              void* d_out, int out_size)
{
    const float* x       = (const float*)d_in[0];
    const float* alpha   = (const float*)d_in[1];
    const float* adj     = (const float*)d_in[2];
    const float* w_alpha = (const float*)d_in[3];
    const float* w_vi    = (const float*)d_in[4];
    const float* w_vj    = (const float*)d_in[5];
    const float* bias_h  = (const float*)d_in[6];
    const float* w_node  = (const float*)d_in[7];

    float* out       = (float*)d_out;
    float* out_x     = out;
    float* out_alpha = out + BB * NN * DD;

    cudaFuncSetAttribute(main_kernel, cudaFuncAttributeMaxDynamicSharedMemorySize, SMEM_BYTES);

    prep1_kernel<<<384, 256>>>(w_alpha, w_vi, w_vj);
    prep2_kernel<<<256, 256>>>(x);
    prep3_kernel<<<512, 256>>>();
    main_kernel<<<BB * NN, 256, SMEM_BYTES>>>(alpha, adj, bias_h, w_node, out_x, out_alpha);
}